// round 15
// baseline (speedup 1.0000x reference)
#include <cuda_runtime.h>
#include <cuda_fp16.h>
#include <cstdint>

static constexpr int Bn = 8, Tn = 1024, Cn = 768, Hn = 12, Dn = 64;
static constexpr int Mn = Bn * Tn;      // 8192
static constexpr int KT = Cn / 16;      // 48 k16 chunks
static constexpr int MT = Mn / 16;      // 512 m16 tiles
static constexpr int NTW = Cn / 8;      // 96 n8 tiles per weight matrix
static constexpr int BH = Bn * Hn;      // 96

// ---------------------------------------------------------------------------
// Scratch device globals
// ---------------------------------------------------------------------------
// A fragments (single fp16): [mt][tk][lane] -> uint4 (a0..a3)
__device__ uint4 g_xfh[MT * KT * 32];
__device__ uint4 g_yfh[MT * KT * 32];
// Weights B-frags (single fp16): [mat][nt][tk][lane] -> uint2 {b0,b1}
__device__ uint2 g_wf[4 * NTW * KT * 32];
// Q A-frags (single fp16, pre-scaled 1/8): [bh][mt(64)][dc(4)][lane]
__device__ uint4 g_qfh[BH * 64 * 4 * 32];
// K B-frags (single): [bh][nt(128)][dc(4)][lane]
__device__ uint2 g_kf[BH * 128 * 4 * 32];
// V^T B-frags (single): [bh][dt(8)][kc(64)][lane]
__device__ uint2 g_vtf[BH * 8 * 64 * 32];

// ---------------------------------------------------------------------------
// Helpers
// ---------------------------------------------------------------------------
__device__ __forceinline__ uint32_t smem_u32(const void* p) {
    uint32_t a;
    asm("{ .reg .u64 t; cvta.to.shared.u64 t, %1; cvt.u32.u64 %0, t; }"
        : "=r"(a) : "l"(p));
    return a;
}
__device__ __forceinline__ void cp16(uint32_t dst, const void* src) {
    asm volatile("cp.async.ca.shared.global [%0], [%1], 16;\n" :: "r"(dst), "l"(src));
}
__device__ __forceinline__ void cp8(uint32_t dst, const void* src) {
    asm volatile("cp.async.ca.shared.global [%0], [%1], 8;\n" :: "r"(dst), "l"(src));
}
#define CP_COMMIT() asm volatile("cp.async.commit_group;\n" ::: "memory")
#define CP_WAIT2()  asm volatile("cp.async.wait_group 2;\n" ::: "memory")
#define CP_WAIT1()  asm volatile("cp.async.wait_group 1;\n" ::: "memory")

__device__ __forceinline__ void mma16816(float* d, const uint32_t* a,
                                         uint32_t b0, uint32_t b1) {
    asm volatile(
        "mma.sync.aligned.m16n8k16.row.col.f32.f16.f16.f32 "
        "{%0,%1,%2,%3}, {%4,%5,%6,%7}, {%8,%9}, {%0,%1,%2,%3};\n"
        : "+f"(d[0]), "+f"(d[1]), "+f"(d[2]), "+f"(d[3])
        : "r"(a[0]), "r"(a[1]), "r"(a[2]), "r"(a[3]), "r"(b0), "r"(b1));
}

__device__ __forceinline__ uint32_t packh(float x, float y) {
    __half2 h = __floats2half2_rn(x, y);
    return *reinterpret_cast<uint32_t*>(&h);
}

// ---------------------------------------------------------------------------
// Combined input split: x -> single fp16 A-frags; W -> single fp16 B-frags
// ---------------------------------------------------------------------------
static constexpr int ACT_BLKS = (MT * KT) / 8;          // 3072
static constexpr int W_BLKS   = (4 * NTW * KT) / 8;     // 2304

__global__ __launch_bounds__(256)
void split_xw_kernel(const float* __restrict__ X,
                     const float* __restrict__ Wq, const float* __restrict__ Wk,
                     const float* __restrict__ Wv, const float* __restrict__ Wp)
{
    int lane = threadIdx.x & 31;
    if (blockIdx.x < ACT_BLKS) {
        int w = (blockIdx.x * 256 + threadIdx.x) >> 5;
        int tm = w / KT, tk = w % KT;
        int row = tm * 16 + (lane >> 2);
        int kc  = tk * 16 + ((lane & 3) << 1);

        float2 v00 = *(const float2*)(X + (size_t)row * Cn + kc);
        float2 v10 = *(const float2*)(X + (size_t)(row + 8) * Cn + kc);
        float2 v01 = *(const float2*)(X + (size_t)row * Cn + kc + 8);
        float2 v11 = *(const float2*)(X + (size_t)(row + 8) * Cn + kc + 8);

        uint4 h;
        h.x = packh(v00.x, v00.y);
        h.y = packh(v10.x, v10.y);
        h.z = packh(v01.x, v01.y);
        h.w = packh(v11.x, v11.y);
        g_xfh[(size_t)w * 32 + lane] = h;
    } else {
        int w = ((blockIdx.x - ACT_BLKS) * 256 + threadIdx.x) >> 5;
        int mat = w / (NTW * KT);
        int rem = w % (NTW * KT);
        int tn = rem / KT, tk = rem % KT;

        const float* W;
        switch (mat) {
            case 0: W = Wq; break;
            case 1: W = Wk; break;
            case 2: W = Wv; break;
            default: W = Wp; break;
        }
        int n  = tn * 8 + (lane >> 2);
        int k0 = tk * 16 + ((lane & 3) << 1);

        uint2 o;
        o.x = packh(W[(size_t)k0 * Cn + n], W[(size_t)(k0 + 1) * Cn + n]);
        o.y = packh(W[(size_t)(k0 + 8) * Cn + n], W[(size_t)(k0 + 9) * Cn + n]);
        g_wf[(size_t)w * 32 + lane] = o;
    }
}

// ---------------------------------------------------------------------------
// fp16 tensor-core GEMM (single-A), templated on NT = n8-tiles per CTA.
// NT=16: 128x128 tile (qkv, modes 1/2/3). NT=12: 128x96 tile (proj, mode 0)
// at 3 CTAs/SM (regs capped to 84) -> 444 slots, 512 CTAs = 1.15 waves.
// 256 threads (8 warps: 4m x 2n). 4-stage cp.async pipeline.
// Stage layout: A [0,4K) mt*512+lane*16, B [4K,4K+NT*256) nt*256+lane*8.
// B copy: warps 0..7 carry tile cp_t; warps with cp_t < NT-8 also carry
// tile cp_t+8.
// Epilogue modes: 0 = fp32 (+bias) to Out; 1 = Q A-frags (single fp16);
//                 2 = K B-frags; 3 = V^T B-frags via smem fp16 transpose.
// ---------------------------------------------------------------------------
static constexpr int GEMM_SMEM_16 = 40960;  // 4 x 8KB stages + V^T transpose headroom
static constexpr int GEMM_SMEM_12 = 28672;  // 4 x 7KB stages

template <int NT>
__device__ __forceinline__ void gemm_mma_body(const uint4* __restrict__ Ah,
                                              const uint2* __restrict__ Wf,
                                              const float* __restrict__ bias,
                                              float* __restrict__ Out,
                                              int mode)
{
    constexpr int STG = 4096 + NT * 256;   // stage bytes
    constexpr int NW  = NT / 2;            // n8-tiles per warp

    extern __shared__ __align__(16) char smem[];
    const uint32_t sbase = smem_u32(smem);
    const int tid  = threadIdx.x;
    const int lane = tid & 31;
    const int wid  = tid >> 5;
    const int wm   = wid >> 1;
    const int wn   = wid & 1;

    const int mtBase = blockIdx.y * 8;
    const int ntBase = blockIdx.x * NT;
    const int cp_t   = wid;
    const bool hasB1 = (cp_t < NT - 8);    // second B tile for this warp

    const uint4* srcAh = Ah + ((size_t)(mtBase + cp_t) * KT) * 32 + lane;
    const uint2* srcB0 = Wf + ((size_t)(ntBase + cp_t) * KT) * 32 + lane;
    const uint2* srcB1 = Wf + ((size_t)(ntBase + cp_t + 8) * KT) * 32 + lane;

    const uint32_t dA0 = sbase + cp_t * 512 + lane * 16;
    const uint32_t dB0 = sbase + 4096 + cp_t * 256 + lane * 8;
    const uint32_t dB1 = dB0 + 2048;

    float d[2][NW][4];
#pragma unroll
    for (int i = 0; i < 2; i++)
#pragma unroll
        for (int j = 0; j < NW; j++)
#pragma unroll
            for (int e = 0; e < 4; e++) d[i][j][e] = 0.f;

    auto issue = [&](int slot, int tk) {
        uint32_t so = (uint32_t)slot * STG;
        cp16(dA0 + so, srcAh + (size_t)tk * 32);
        cp8(dB0 + so, srcB0 + (size_t)tk * 32);
        if (hasB1) cp8(dB1 + so, srcB1 + (size_t)tk * 32);
    };

    issue(0, 0); CP_COMMIT();
    issue(1, 1); CP_COMMIT();
    issue(2, 2); CP_COMMIT();

    for (int k = 0; k < KT; k++) {
        CP_WAIT2();
        __syncthreads();
        if (k + 3 < KT) issue((k + 3) & 3, k + 3);
        CP_COMMIT();

        const char* stg = smem + (size_t)(k & 3) * STG;
        uint4 ah0 = *(const uint4*)(stg + (wm * 2 + 0) * 512 + lane * 16);
        uint4 ah1 = *(const uint4*)(stg + (wm * 2 + 1) * 512 + lane * 16);
#pragma unroll
        for (int nt = 0; nt < NW; nt++) {
            uint2 b = *(const uint2*)(stg + 4096 + (wn * NW + nt) * 256 + lane * 8);
            mma16816(d[0][nt], (const uint32_t*)&ah0, b.x, b.y);
            mma16816(d[1][nt], (const uint32_t*)&ah1, b.x, b.y);
        }
    }

    const int cb = blockIdx.x * (NT * 8) + wn * (NW * 8) + ((lane & 3) << 1);
    const int h  = blockIdx.x * 2 + wn;   // head (NT=16 modes only)

    if (NT == 16 && mode == 3) {
        // V^T fragments via smem fp16 transpose (row stride 136 halves).
        __syncthreads();
        __half* sv = reinterpret_cast<__half*>(smem);
#pragma unroll
        for (int mt = 0; mt < 2; mt++) {
            int r = wm * 32 + mt * 16 + (lane >> 2);
#pragma unroll
            for (int nt = 0; nt < NW; nt++) {
                int cl  = wn * 64 + nt * 8 + ((lane & 3) << 1);
                int col = blockIdx.x * 128 + cl;
                float bx = bias[col], by = bias[col + 1];
                *(__half2*)&sv[r * 136 + cl] =
                    __floats2half2_rn(d[mt][nt][0] + bx, d[mt][nt][1] + by);
                *(__half2*)&sv[(r + 8) * 136 + cl] =
                    __floats2half2_rn(d[mt][nt][2] + bx, d[mt][nt][3] + by);
            }
        }
        __syncthreads();
        const ushort* su = reinterpret_cast<const ushort*>(sv);
        const int bb  = blockIdx.y >> 3;
        const int kcb = (blockIdx.y & 7) * 8;
        const int dt  = wid;
#pragma unroll
        for (int hh = 0; hh < 2; hh++) {
            int dl  = hh * 64 + dt * 8 + (lane >> 2);
            int bh2 = bb * Hn + blockIdx.x * 2 + hh;
#pragma unroll
            for (int kl = 0; kl < 8; kl++) {
                int k0 = kl * 16 + ((lane & 3) << 1);
                uint2 o;
                o.x = (uint32_t)su[k0 * 136 + dl] |
                      ((uint32_t)su[(k0 + 1) * 136 + dl] << 16);
                o.y = (uint32_t)su[(k0 + 8) * 136 + dl] |
                      ((uint32_t)su[(k0 + 9) * 136 + dl] << 16);
                g_vtf[(((size_t)bh2 * 8 + dt) * 64 + kcb + kl) * 32 + lane] = o;
            }
        }
        return;
    }

#pragma unroll
    for (int mt = 0; mt < 2; mt++) {
        const int rg = blockIdx.y * 128 + wm * 32 + mt * 16;
        if (mode == 0) {
            const int r0 = rg + (lane >> 2);
#pragma unroll
            for (int nt = 0; nt < NW; nt++) {
                int col = cb + nt * 8;
                float bx = bias[col], by = bias[col + 1];
                *(float2*)(Out + (size_t)r0 * Cn + col) =
                    make_float2(d[mt][nt][0] + bx, d[mt][nt][1] + by);
                *(float2*)(Out + (size_t)(r0 + 8) * Cn + col) =
                    make_float2(d[mt][nt][2] + bx, d[mt][nt][3] + by);
            }
        } else if (NT == 16 && mode == 1) {
            // Q A-fragments (single fp16): scale 1/8, bias folded
            const int bq_ = rg >> 10;
            const int mtq = (rg & 1023) >> 4;
            const size_t base =
                ((size_t)((bq_ * Hn + h) * 64 + mtq) * 4) * 32 + lane;
#pragma unroll
            for (int dc = 0; dc < 4; dc++) {
                int c0 = cb + (2 * dc) * 8, c1 = cb + (2 * dc + 1) * 8;
                float b00 = bias[c0], b01 = bias[c0 + 1];
                float b10 = bias[c1], b11 = bias[c1 + 1];
                uint4 hh;
                hh.x = packh((d[mt][2*dc][0]   + b00) * 0.125f,
                             (d[mt][2*dc][1]   + b01) * 0.125f);
                hh.y = packh((d[mt][2*dc][2]   + b00) * 0.125f,
                             (d[mt][2*dc][3]   + b01) * 0.125f);
                hh.z = packh((d[mt][2*dc+1][0] + b10) * 0.125f,
                             (d[mt][2*dc+1][1] + b11) * 0.125f);
                hh.w = packh((d[mt][2*dc+1][2] + b10) * 0.125f,
                             (d[mt][2*dc+1][3] + b11) * 0.125f);
                g_qfh[base + dc * 32] = hh;
            }
        } else if (NT == 16) {
            // K B-fragments (single fp16): two n8 key-tiles per m16
            const int bq_ = rg >> 10;
            const int ntk = (rg & 1023) >> 3;
            const size_t base =
                ((size_t)((bq_ * Hn + h) * 128 + ntk) * 4) * 32 + lane;
#pragma unroll
            for (int dc = 0; dc < 4; dc++) {
                int c0 = cb + (2 * dc) * 8, c1 = cb + (2 * dc + 1) * 8;
                float b00 = bias[c0], b01 = bias[c0 + 1];
                float b10 = bias[c1], b11 = bias[c1 + 1];
                uint2 t0, t1;
                t0.x = packh(d[mt][2*dc][0]   + b00, d[mt][2*dc][1]   + b01);
                t0.y = packh(d[mt][2*dc+1][0] + b10, d[mt][2*dc+1][1] + b11);
                t1.x = packh(d[mt][2*dc][2]   + b00, d[mt][2*dc][3]   + b01);
                t1.y = packh(d[mt][2*dc+1][2] + b10, d[mt][2*dc+1][3] + b11);
                g_kf[base + dc * 32]          = t0;
                g_kf[base + 4 * 32 + dc * 32] = t1;
            }
        }
    }
}

__global__ __launch_bounds__(256, 2)
void qkv_mma(const float* __restrict__ bq, const float* __restrict__ bk,
             const float* __restrict__ bv)
{
    const uint2* Wf = g_wf + (size_t)blockIdx.z * NTW * KT * 32;
    if (blockIdx.z == 0)      gemm_mma_body<16>(g_xfh, Wf, bq, nullptr, 1);
    else if (blockIdx.z == 1) gemm_mma_body<16>(g_xfh, Wf, bk, nullptr, 2);
    else                      gemm_mma_body<16>(g_xfh, Wf, bv, nullptr, 3);
}

__global__ __launch_bounds__(256, 3)
void proj_mma(const float* __restrict__ bp, float* __restrict__ out)
{
    gemm_mma_body<12>(g_yfh, g_wf + (size_t)3 * NTW * KT * 32, bp, out, 0);
}

// ---------------------------------------------------------------------------
// fp16 tensor-core flash attention (unchanged from R11).
// Block = (64 q-rows, head, batch), 128 threads = 4 warps (m16 each).
// CTA order reversed so the longest q-tiles launch first.
// ---------------------------------------------------------------------------
static constexpr int ATT_STG  = 16384;
static constexpr int ATT_SMEM = 3 * ATT_STG;   // 48KB

__global__ __launch_bounds__(128, 1)
void attn_mma()
{
    extern __shared__ __align__(16) char smem[];
    const uint32_t sbase = smem_u32(smem);
    const int tid  = threadIdx.x;
    const int lane = tid & 31;
    const int w    = tid >> 5;
    const int qt   = gridDim.x - 1 - blockIdx.x;
    const int h    = blockIdx.y;
    const int b    = blockIdx.z;
    const int bh   = b * Hn + h;
    const int nkt  = qt + 1;

    uint4 qh[4];
    {
        const uint4* Qh = g_qfh + ((size_t)(bh * 64 + qt * 4 + w) * 4) * 32 + lane;
#pragma unroll
        for (int dc = 0; dc < 4; dc++) qh[dc] = Qh[dc * 32];
    }

    float o[8][4];
#pragma unroll
    for (int i = 0; i < 8; i++)
#pragma unroll
        for (int j = 0; j < 4; j++) o[i][j] = 0.f;
    float m[2] = {-1e30f, -1e30f}, l[2] = {0.f, 0.f};

    const uint2* Ksrc = g_kf  + (size_t)bh * 128 * 4 * 32;
    const uint2* Vsrc = g_vtf + (size_t)bh * 8 * 64 * 32;
    const int vkc = w;

    auto issue = [&](int slot, int kt) {
        uint32_t so = sbase + (uint32_t)slot * ATT_STG;
        const uint2* ks = Ksrc + (size_t)kt * 1024;
#pragma unroll
        for (int i = 0; i < 8; i++)
            cp8(so + (uint32_t)(i * 128 + tid) * 8, ks + i * 128 + tid);
#pragma unroll
        for (int dt = 0; dt < 8; dt++)
            cp8(so + 8192 + (uint32_t)((dt * 4 + vkc) * 32 + lane) * 8,
                Vsrc + ((size_t)dt * 64 + kt * 4 + vkc) * 32 + lane);
    };

    issue(0, 0); CP_COMMIT();
    if (nkt > 1) issue(1, 1);
    CP_COMMIT();

    for (int kt = 0; kt < nkt; kt++) {
        CP_WAIT1();
        __syncthreads();
        if (kt + 2 < nkt) issue((kt + 2) % 3, kt + 2);
        CP_COMMIT();

        const char* stK = smem + (size_t)(kt % 3) * ATT_STG;
        const char* stV = stK + 8192;

        // S = Q @ K^T (both single fp16)
        float s[8][4];
#pragma unroll
        for (int i = 0; i < 8; i++)
#pragma unroll
            for (int j = 0; j < 4; j++) s[i][j] = 0.f;
#pragma unroll
        for (int dc = 0; dc < 4; dc++) {
#pragma unroll
            for (int nt = 0; nt < 8; nt++) {
                uint2 kb = *(const uint2*)(stK + ((nt * 4 + dc) * 32 + lane) * 8);
                mma16816(s[nt], (const uint32_t*)&qh[dc], kb.x, kb.y);
            }
        }

        // Causal mask (diagonal tile only)
        if (kt == qt) {
            int r0 = w * 16 + (lane >> 2);
            int c0 = (lane & 3) << 1;
#pragma unroll
            for (int nt = 0; nt < 8; nt++) {
                int col = nt * 8 + c0;
                if (col > r0)         s[nt][0] = -1e30f;
                if (col + 1 > r0)     s[nt][1] = -1e30f;
                if (col > r0 + 8)     s[nt][2] = -1e30f;
                if (col + 1 > r0 + 8) s[nt][3] = -1e30f;
            }
        }

        // Online softmax per row-half
#pragma unroll
        for (int i = 0; i < 2; i++) {
            float tm = -1e30f;
#pragma unroll
            for (int nt = 0; nt < 8; nt++)
                tm = fmaxf(tm, fmaxf(s[nt][2 * i], s[nt][2 * i + 1]));
            tm = fmaxf(tm, __shfl_xor_sync(0xffffffffu, tm, 1));
            tm = fmaxf(tm, __shfl_xor_sync(0xffffffffu, tm, 2));
            float newm = fmaxf(m[i], tm);
            float fac  = __expf(m[i] - newm);
            m[i] = newm;
            float rs = 0.f;
#pragma unroll
            for (int nt = 0; nt < 8; nt++) {
                float p0 = __expf(s[nt][2 * i] - newm);
                float p1 = __expf(s[nt][2 * i + 1] - newm);
                s[nt][2 * i] = p0;
                s[nt][2 * i + 1] = p1;
                rs += p0 + p1;
            }
            rs += __shfl_xor_sync(0xffffffffu, rs, 1);
            rs += __shfl_xor_sync(0xffffffffu, rs, 2);
            l[i] = l[i] * fac + rs;
#pragma unroll
            for (int dt = 0; dt < 8; dt++) {
                o[dt][2 * i]     *= fac;
                o[dt][2 * i + 1] *= fac;
            }
        }

        // O += P @ V  (P single fp16)
#pragma unroll
        for (int t = 0; t < 4; t++) {
            uint32_t ph[4];
            ph[0] = packh(s[2*t][0],   s[2*t][1]);
            ph[1] = packh(s[2*t][2],   s[2*t][3]);
            ph[2] = packh(s[2*t+1][0], s[2*t+1][1]);
            ph[3] = packh(s[2*t+1][2], s[2*t+1][3]);
#pragma unroll
            for (int dt = 0; dt < 8; dt++) {
                uint2 v = *(const uint2*)(stV + ((dt * 4 + t) * 32 + lane) * 8);
                mma16816(o[dt], ph, v.x, v.y);
            }
        }
    }

    // Epilogue: normalize, write y A-fragments (single fp16) for proj GEMM
    const float inv0 = 1.f / l[0];
    const float inv1 = 1.f / l[1];
    const int mtg = b * 64 + qt * 4 + w;
#pragma unroll
    for (int dtc = 0; dtc < 4; dtc++) {
        uint4 hh;
        hh.x = packh(o[2*dtc][0]   * inv0, o[2*dtc][1]   * inv0);
        hh.y = packh(o[2*dtc][2]   * inv1, o[2*dtc][3]   * inv1);
        hh.z = packh(o[2*dtc+1][0] * inv0, o[2*dtc+1][1] * inv0);
        hh.w = packh(o[2*dtc+1][2] * inv1, o[2*dtc+1][3] * inv1);
        size_t idx = ((size_t)mtg * KT + h * 4 + dtc) * 32 + lane;
        g_yfh[idx] = hh;
    }
}

// ---------------------------------------------------------------------------
extern "C" void kernel_launch(void* const* d_in, const int* in_sizes, int n_in,
                              void* d_out, int out_size)
{
    const float* x  = (const float*)d_in[0];
    const float* Wq = (const float*)d_in[1];
    const float* bq = (const float*)d_in[2];
    const float* Wk = (const float*)d_in[3];
    const float* bk = (const float*)d_in[4];
    const float* Wv = (const float*)d_in[5];
    const float* bv = (const float*)d_in[6];
    const float* Wp = (const float*)d_in[7];
    const float* bp = (const float*)d_in[8];
    float* out = (float*)d_out;

    cudaFuncSetAttribute(qkv_mma, cudaFuncAttributeMaxDynamicSharedMemorySize, GEMM_SMEM_16);
    cudaFuncSetAttribute(proj_mma, cudaFuncAttributeMaxDynamicSharedMemorySize, GEMM_SMEM_12);
    cudaFuncSetAttribute(attn_mma, cudaFuncAttributeMaxDynamicSharedMemorySize, ATT_SMEM);

    split_xw_kernel<<<ACT_BLKS + W_BLKS, 256>>>(x, Wq, Wk, Wv, Wp);
    qkv_mma<<<dim3(Cn / 128, Mn / 128, 3), 256, GEMM_SMEM_16>>>(bq, bk, bv);
    attn_mma<<<dim3(Tn / 64, Hn, Bn), 128, ATT_SMEM>>>();
    proj_mma<<<dim3(Cn / 96, Mn / 128, 1), 256, GEMM_SMEM_12>>>(bp, out);
}

// round 16
// speedup vs baseline: 1.0786x; 1.0786x over previous
#include <cuda_runtime.h>
#include <cuda_fp16.h>
#include <cstdint>

static constexpr int Bn = 8, Tn = 1024, Cn = 768, Hn = 12, Dn = 64;
static constexpr int Mn = Bn * Tn;      // 8192
static constexpr int KT = Cn / 16;      // 48 k16 chunks
static constexpr int MT = Mn / 16;      // 512 m16 tiles
static constexpr int NTW = Cn / 8;      // 96 n8 tiles per weight matrix
static constexpr int BH = Bn * Hn;      // 96

// ---------------------------------------------------------------------------
// Scratch device globals
// ---------------------------------------------------------------------------
// A fragments (single fp16): [mt][tk][lane] -> uint4 (a0..a3)
__device__ uint4 g_xfh[MT * KT * 32];
__device__ uint4 g_yfh[MT * KT * 32];
// Weights B-frags (single fp16): [mat][nt][tk][lane] -> uint2 {b0,b1}
__device__ uint2 g_wf[4 * NTW * KT * 32];
// Q A-frags (single fp16, pre-scaled by log2e/8): [bh][mt(64)][dc(4)][lane]
__device__ uint4 g_qfh[BH * 64 * 4 * 32];
// K B-frags (single): [bh][nt(128)][dc(4)][lane]
__device__ uint2 g_kf[BH * 128 * 4 * 32];
// V^T B-frags (single): [bh][dt(8)][kc(64)][lane]
__device__ uint2 g_vtf[BH * 8 * 64 * 32];

// ---------------------------------------------------------------------------
// Helpers
// ---------------------------------------------------------------------------
__device__ __forceinline__ uint32_t smem_u32(const void* p) {
    uint32_t a;
    asm("{ .reg .u64 t; cvta.to.shared.u64 t, %1; cvt.u32.u64 %0, t; }"
        : "=r"(a) : "l"(p));
    return a;
}
__device__ __forceinline__ void cp16(uint32_t dst, const void* src) {
    asm volatile("cp.async.ca.shared.global [%0], [%1], 16;\n" :: "r"(dst), "l"(src));
}
__device__ __forceinline__ void cp8(uint32_t dst, const void* src) {
    asm volatile("cp.async.ca.shared.global [%0], [%1], 8;\n" :: "r"(dst), "l"(src));
}
#define CP_COMMIT() asm volatile("cp.async.commit_group;\n" ::: "memory")
#define CP_WAIT2()  asm volatile("cp.async.wait_group 2;\n" ::: "memory")
#define CP_WAIT1()  asm volatile("cp.async.wait_group 1;\n" ::: "memory")

__device__ __forceinline__ void mma16816(float* d, const uint32_t* a,
                                         uint32_t b0, uint32_t b1) {
    asm volatile(
        "mma.sync.aligned.m16n8k16.row.col.f32.f16.f16.f32 "
        "{%0,%1,%2,%3}, {%4,%5,%6,%7}, {%8,%9}, {%0,%1,%2,%3};\n"
        : "+f"(d[0]), "+f"(d[1]), "+f"(d[2]), "+f"(d[3])
        : "r"(a[0]), "r"(a[1]), "r"(a[2]), "r"(a[3]), "r"(b0), "r"(b1));
}

__device__ __forceinline__ uint32_t packh(float x, float y) {
    __half2 h = __floats2half2_rn(x, y);
    return *reinterpret_cast<uint32_t*>(&h);
}

// ---------------------------------------------------------------------------
// Combined input split: x -> single fp16 A-frags; W -> single fp16 B-frags
// ---------------------------------------------------------------------------
static constexpr int ACT_BLKS = (MT * KT) / 8;          // 3072
static constexpr int W_BLKS   = (4 * NTW * KT) / 8;     // 2304

__global__ __launch_bounds__(256)
void split_xw_kernel(const float* __restrict__ X,
                     const float* __restrict__ Wq, const float* __restrict__ Wk,
                     const float* __restrict__ Wv, const float* __restrict__ Wp)
{
    int lane = threadIdx.x & 31;
    if (blockIdx.x < ACT_BLKS) {
        int w = (blockIdx.x * 256 + threadIdx.x) >> 5;
        int tm = w / KT, tk = w % KT;
        int row = tm * 16 + (lane >> 2);
        int kc  = tk * 16 + ((lane & 3) << 1);

        float2 v00 = *(const float2*)(X + (size_t)row * Cn + kc);
        float2 v10 = *(const float2*)(X + (size_t)(row + 8) * Cn + kc);
        float2 v01 = *(const float2*)(X + (size_t)row * Cn + kc + 8);
        float2 v11 = *(const float2*)(X + (size_t)(row + 8) * Cn + kc + 8);

        uint4 h;
        h.x = packh(v00.x, v00.y);
        h.y = packh(v10.x, v10.y);
        h.z = packh(v01.x, v01.y);
        h.w = packh(v11.x, v11.y);
        g_xfh[(size_t)w * 32 + lane] = h;
    } else {
        int w = ((blockIdx.x - ACT_BLKS) * 256 + threadIdx.x) >> 5;
        int mat = w / (NTW * KT);
        int rem = w % (NTW * KT);
        int tn = rem / KT, tk = rem % KT;

        const float* W;
        switch (mat) {
            case 0: W = Wq; break;
            case 1: W = Wk; break;
            case 2: W = Wv; break;
            default: W = Wp; break;
        }
        int n  = tn * 8 + (lane >> 2);
        int k0 = tk * 16 + ((lane & 3) << 1);

        uint2 o;
        o.x = packh(W[(size_t)k0 * Cn + n], W[(size_t)(k0 + 1) * Cn + n]);
        o.y = packh(W[(size_t)(k0 + 8) * Cn + n], W[(size_t)(k0 + 9) * Cn + n]);
        g_wf[(size_t)w * 32 + lane] = o;
    }
}

// ---------------------------------------------------------------------------
// fp16 tensor-core GEMM (single-A), NT = n8-tiles per CTA (16 everywhere).
// 256 threads (8 warps: 4m x 2n). 4-stage cp.async pipeline, 8KB/stage.
// Stage layout: A [0,4K) mt*512+lane*16, B [4K,8K) nt*256+lane*8.
// B copy: one cp16 per thread — lanes 0..15 carry tile cp_t (B0),
// lanes 16..31 carry tile cp_t+8 (B1).
// Epilogue modes: 0 = fp32 (+bias) to Out; 1 = Q A-frags (single fp16,
// scale log2e/8); 2 = K B-frags; 3 = V^T B-frags via smem fp16 transpose.
// ---------------------------------------------------------------------------
static constexpr int GEMM_SMEM_16 = 40960;  // 4 x 8KB stages + V^T transpose headroom

template <int NT>
__device__ __forceinline__ void gemm_mma_body(const uint4* __restrict__ Ah,
                                              const uint2* __restrict__ Wf,
                                              const float* __restrict__ bias,
                                              float* __restrict__ Out,
                                              int mode)
{
    constexpr int STG = 4096 + NT * 256;   // stage bytes
    constexpr int NW  = NT / 2;            // n8-tiles per warp

    extern __shared__ __align__(16) char smem[];
    const uint32_t sbase = smem_u32(smem);
    const int tid  = threadIdx.x;
    const int lane = tid & 31;
    const int wid  = tid >> 5;
    const int wm   = wid >> 1;
    const int wn   = wid & 1;

    const int mtBase = blockIdx.y * 8;
    const int ntBase = blockIdx.x * NT;
    const int cp_t   = wid;

    // B copy role: lanes 0..15 -> B0 tile (cp_t), lanes 16..31 -> B1 (cp_t+8)
    const int  bl   = lane & 15;
    const bool loB  = (lane < 16);
    const bool actB = loB || (cp_t < NT - 8);

    const uint4* srcAh = Ah + ((size_t)(mtBase + cp_t) * KT) * 32 + lane;
    const uint2* srcB  = Wf + ((size_t)(ntBase + cp_t + (loB ? 0 : 8)) * KT) * 32
                            + 2 * bl;

    const uint32_t dA0 = sbase + cp_t * 512 + lane * 16;
    const uint32_t dB  = sbase + 4096 + cp_t * 256 + (loB ? 0u : 2048u) + bl * 16;

    float d[2][NW][4];
#pragma unroll
    for (int i = 0; i < 2; i++)
#pragma unroll
        for (int j = 0; j < NW; j++)
#pragma unroll
            for (int e = 0; e < 4; e++) d[i][j][e] = 0.f;

    auto issue = [&](int slot, int tk) {
        uint32_t so = (uint32_t)slot * STG;
        cp16(dA0 + so, srcAh + (size_t)tk * 32);
        if (actB) cp16(dB + so, srcB + (size_t)tk * 32);
    };

    issue(0, 0); CP_COMMIT();
    issue(1, 1); CP_COMMIT();
    issue(2, 2); CP_COMMIT();

    for (int k = 0; k < KT; k++) {
        CP_WAIT2();
        __syncthreads();
        if (k + 3 < KT) issue((k + 3) & 3, k + 3);
        CP_COMMIT();

        const char* stg = smem + (size_t)(k & 3) * STG;
        uint4 ah0 = *(const uint4*)(stg + (wm * 2 + 0) * 512 + lane * 16);
        uint4 ah1 = *(const uint4*)(stg + (wm * 2 + 1) * 512 + lane * 16);
#pragma unroll
        for (int nt = 0; nt < NW; nt++) {
            uint2 b = *(const uint2*)(stg + 4096 + (wn * NW + nt) * 256 + lane * 8);
            mma16816(d[0][nt], (const uint32_t*)&ah0, b.x, b.y);
            mma16816(d[1][nt], (const uint32_t*)&ah1, b.x, b.y);
        }
    }

    const int cb = blockIdx.x * (NT * 8) + wn * (NW * 8) + ((lane & 3) << 1);
    const int h  = blockIdx.x * 2 + wn;   // head (modes 1/2/3)

    if (NT == 16 && mode == 3) {
        // V^T fragments via smem fp16 transpose (row stride 136 halves).
        __syncthreads();
        __half* sv = reinterpret_cast<__half*>(smem);
#pragma unroll
        for (int mt = 0; mt < 2; mt++) {
            int r = wm * 32 + mt * 16 + (lane >> 2);
#pragma unroll
            for (int nt = 0; nt < NW; nt++) {
                int cl  = wn * 64 + nt * 8 + ((lane & 3) << 1);
                int col = blockIdx.x * 128 + cl;
                float bx = bias[col], by = bias[col + 1];
                *(__half2*)&sv[r * 136 + cl] =
                    __floats2half2_rn(d[mt][nt][0] + bx, d[mt][nt][1] + by);
                *(__half2*)&sv[(r + 8) * 136 + cl] =
                    __floats2half2_rn(d[mt][nt][2] + bx, d[mt][nt][3] + by);
            }
        }
        __syncthreads();
        const ushort* su = reinterpret_cast<const ushort*>(sv);
        const int bb  = blockIdx.y >> 3;
        const int kcb = (blockIdx.y & 7) * 8;
        const int dt  = wid;
#pragma unroll
        for (int hh = 0; hh < 2; hh++) {
            int dl  = hh * 64 + dt * 8 + (lane >> 2);
            int bh2 = bb * Hn + blockIdx.x * 2 + hh;
#pragma unroll
            for (int kl = 0; kl < 8; kl++) {
                int k0 = kl * 16 + ((lane & 3) << 1);
                uint2 o;
                o.x = (uint32_t)su[k0 * 136 + dl] |
                      ((uint32_t)su[(k0 + 1) * 136 + dl] << 16);
                o.y = (uint32_t)su[(k0 + 8) * 136 + dl] |
                      ((uint32_t)su[(k0 + 9) * 136 + dl] << 16);
                g_vtf[(((size_t)bh2 * 8 + dt) * 64 + kcb + kl) * 32 + lane] = o;
            }
        }
        return;
    }

#pragma unroll
    for (int mt = 0; mt < 2; mt++) {
        const int rg = blockIdx.y * 128 + wm * 32 + mt * 16;
        if (mode == 0) {
            const int r0 = rg + (lane >> 2);
#pragma unroll
            for (int nt = 0; nt < NW; nt++) {
                int col = cb + nt * 8;
                float bx = bias[col], by = bias[col + 1];
                *(float2*)(Out + (size_t)r0 * Cn + col) =
                    make_float2(d[mt][nt][0] + bx, d[mt][nt][1] + by);
                *(float2*)(Out + (size_t)(r0 + 8) * Cn + col) =
                    make_float2(d[mt][nt][2] + bx, d[mt][nt][3] + by);
            }
        } else if (NT == 16 && mode == 1) {
            // Q A-fragments (single fp16): scale log2e/8, bias folded
            const float QS = 0.18033688f;   // 0.125 * log2(e)
            const int bq_ = rg >> 10;
            const int mtq = (rg & 1023) >> 4;
            const size_t base =
                ((size_t)((bq_ * Hn + h) * 64 + mtq) * 4) * 32 + lane;
#pragma unroll
            for (int dc = 0; dc < 4; dc++) {
                int c0 = cb + (2 * dc) * 8, c1 = cb + (2 * dc + 1) * 8;
                float b00 = bias[c0], b01 = bias[c0 + 1];
                float b10 = bias[c1], b11 = bias[c1 + 1];
                uint4 hh;
                hh.x = packh((d[mt][2*dc][0]   + b00) * QS,
                             (d[mt][2*dc][1]   + b01) * QS);
                hh.y = packh((d[mt][2*dc][2]   + b00) * QS,
                             (d[mt][2*dc][3]   + b01) * QS);
                hh.z = packh((d[mt][2*dc+1][0] + b10) * QS,
                             (d[mt][2*dc+1][1] + b11) * QS);
                hh.w = packh((d[mt][2*dc+1][2] + b10) * QS,
                             (d[mt][2*dc+1][3] + b11) * QS);
                g_qfh[base + dc * 32] = hh;
            }
        } else if (NT == 16) {
            // K B-fragments (single fp16): two n8 key-tiles per m16
            const int bq_ = rg >> 10;
            const int ntk = (rg & 1023) >> 3;
            const size_t base =
                ((size_t)((bq_ * Hn + h) * 128 + ntk) * 4) * 32 + lane;
#pragma unroll
            for (int dc = 0; dc < 4; dc++) {
                int c0 = cb + (2 * dc) * 8, c1 = cb + (2 * dc + 1) * 8;
                float b00 = bias[c0], b01 = bias[c0 + 1];
                float b10 = bias[c1], b11 = bias[c1 + 1];
                uint2 t0, t1;
                t0.x = packh(d[mt][2*dc][0]   + b00, d[mt][2*dc][1]   + b01);
                t0.y = packh(d[mt][2*dc+1][0] + b10, d[mt][2*dc+1][1] + b11);
                t1.x = packh(d[mt][2*dc][2]   + b00, d[mt][2*dc][3]   + b01);
                t1.y = packh(d[mt][2*dc+1][2] + b10, d[mt][2*dc+1][3] + b11);
                g_kf[base + dc * 32]          = t0;
                g_kf[base + 4 * 32 + dc * 32] = t1;
            }
        }
    }
}

__global__ __launch_bounds__(256, 2)
void qkv_mma(const float* __restrict__ bq, const float* __restrict__ bk,
             const float* __restrict__ bv)
{
    const uint2* Wf = g_wf + (size_t)blockIdx.z * NTW * KT * 32;
    if (blockIdx.z == 0)      gemm_mma_body<16>(g_xfh, Wf, bq, nullptr, 1);
    else if (blockIdx.z == 1) gemm_mma_body<16>(g_xfh, Wf, bk, nullptr, 2);
    else                      gemm_mma_body<16>(g_xfh, Wf, bv, nullptr, 3);
}

__global__ __launch_bounds__(256, 2)
void proj_mma(const float* __restrict__ bp, float* __restrict__ out)
{
    gemm_mma_body<16>(g_yfh, g_wf + (size_t)3 * NTW * KT * 32, bp, out, 0);
}

// ---------------------------------------------------------------------------
// fp16 tensor-core flash attention. exp2-domain softmax (log2e folded into Q).
// Block = (64 q-rows, head, batch), 128 threads = 4 warps (m16 each).
// K tile copied as contiguous 8KB via cp16. CTA order reversed.
// ---------------------------------------------------------------------------
static constexpr int ATT_STG  = 16384;
static constexpr int ATT_SMEM = 3 * ATT_STG;   // 48KB

__global__ __launch_bounds__(128, 1)
void attn_mma()
{
    extern __shared__ __align__(16) char smem[];
    const uint32_t sbase = smem_u32(smem);
    const int tid  = threadIdx.x;
    const int lane = tid & 31;
    const int w    = tid >> 5;
    const int qt   = gridDim.x - 1 - blockIdx.x;
    const int h    = blockIdx.y;
    const int b    = blockIdx.z;
    const int bh   = b * Hn + h;
    const int nkt  = qt + 1;

    uint4 qh[4];
    {
        const uint4* Qh = g_qfh + ((size_t)(bh * 64 + qt * 4 + w) * 4) * 32 + lane;
#pragma unroll
        for (int dc = 0; dc < 4; dc++) qh[dc] = Qh[dc * 32];
    }

    float o[8][4];
#pragma unroll
    for (int i = 0; i < 8; i++)
#pragma unroll
        for (int j = 0; j < 4; j++) o[i][j] = 0.f;
    float m[2] = {-1e30f, -1e30f}, l[2] = {0.f, 0.f};

    const uint2* Ksrc = g_kf  + (size_t)bh * 128 * 4 * 32;
    const uint2* Vsrc = g_vtf + (size_t)bh * 8 * 64 * 32;
    const int vkc = w;

    auto issue = [&](int slot, int kt) {
        uint32_t so = sbase + (uint32_t)slot * ATT_STG;
        // K tile: contiguous 8KB in both gmem and smem -> 4 x cp16
        const char* ksb = (const char*)(Ksrc + (size_t)kt * 1024);
#pragma unroll
        for (int j = 0; j < 4; j++)
            cp16(so + (uint32_t)(j * 128 + tid) * 16, ksb + (size_t)(j * 128 + tid) * 16);
#pragma unroll
        for (int dt = 0; dt < 8; dt++)
            cp8(so + 8192 + (uint32_t)((dt * 4 + vkc) * 32 + lane) * 8,
                Vsrc + ((size_t)dt * 64 + kt * 4 + vkc) * 32 + lane);
    };

    issue(0, 0); CP_COMMIT();
    if (nkt > 1) issue(1, 1);
    CP_COMMIT();

    for (int kt = 0; kt < nkt; kt++) {
        CP_WAIT1();
        __syncthreads();
        if (kt + 2 < nkt) issue((kt + 2) % 3, kt + 2);
        CP_COMMIT();

        const char* stK = smem + (size_t)(kt % 3) * ATT_STG;
        const char* stV = stK + 8192;

        // S = Q @ K^T (both single fp16; logits in log2 domain)
        float s[8][4];
#pragma unroll
        for (int i = 0; i < 8; i++)
#pragma unroll
            for (int j = 0; j < 4; j++) s[i][j] = 0.f;
#pragma unroll
        for (int dc = 0; dc < 4; dc++) {
#pragma unroll
            for (int nt = 0; nt < 8; nt++) {
                uint2 kb = *(const uint2*)(stK + ((nt * 4 + dc) * 32 + lane) * 8);
                mma16816(s[nt], (const uint32_t*)&qh[dc], kb.x, kb.y);
            }
        }

        // Causal mask (diagonal tile only)
        if (kt == qt) {
            int r0 = w * 16 + (lane >> 2);
            int c0 = (lane & 3) << 1;
#pragma unroll
            for (int nt = 0; nt < 8; nt++) {
                int col = nt * 8 + c0;
                if (col > r0)         s[nt][0] = -1e30f;
                if (col + 1 > r0)     s[nt][1] = -1e30f;
                if (col > r0 + 8)     s[nt][2] = -1e30f;
                if (col + 1 > r0 + 8) s[nt][3] = -1e30f;
            }
        }

        // Online softmax per row-half (exp2 domain)
#pragma unroll
        for (int i = 0; i < 2; i++) {
            float tm = -1e30f;
#pragma unroll
            for (int nt = 0; nt < 8; nt++)
                tm = fmaxf(tm, fmaxf(s[nt][2 * i], s[nt][2 * i + 1]));
            tm = fmaxf(tm, __shfl_xor_sync(0xffffffffu, tm, 1));
            tm = fmaxf(tm, __shfl_xor_sync(0xffffffffu, tm, 2));
            float newm = fmaxf(m[i], tm);
            float fac  = exp2f(m[i] - newm);
            m[i] = newm;
            float rs = 0.f;
#pragma unroll
            for (int nt = 0; nt < 8; nt++) {
                float p0 = exp2f(s[nt][2 * i] - newm);
                float p1 = exp2f(s[nt][2 * i + 1] - newm);
                s[nt][2 * i] = p0;
                s[nt][2 * i + 1] = p1;
                rs += p0 + p1;
            }
            rs += __shfl_xor_sync(0xffffffffu, rs, 1);
            rs += __shfl_xor_sync(0xffffffffu, rs, 2);
            l[i] = l[i] * fac + rs;
#pragma unroll
            for (int dt = 0; dt < 8; dt++) {
                o[dt][2 * i]     *= fac;
                o[dt][2 * i + 1] *= fac;
            }
        }

        // O += P @ V  (P single fp16)
#pragma unroll
        for (int t = 0; t < 4; t++) {
            uint32_t ph[4];
            ph[0] = packh(s[2*t][0],   s[2*t][1]);
            ph[1] = packh(s[2*t][2],   s[2*t][3]);
            ph[2] = packh(s[2*t+1][0], s[2*t+1][1]);
            ph[3] = packh(s[2*t+1][2], s[2*t+1][3]);
#pragma unroll
            for (int dt = 0; dt < 8; dt++) {
                uint2 v = *(const uint2*)(stV + ((dt * 4 + t) * 32 + lane) * 8);
                mma16816(o[dt], ph, v.x, v.y);
            }
        }
    }

    // Epilogue: normalize, write y A-fragments (single fp16) for proj GEMM
    const float inv0 = 1.f / l[0];
    const float inv1 = 1.f / l[1];
    const int mtg = b * 64 + qt * 4 + w;
#pragma unroll
    for (int dtc = 0; dtc < 4; dtc++) {
        uint4 hh;
        hh.x = packh(o[2*dtc][0]   * inv0, o[2*dtc][1]   * inv0);
        hh.y = packh(o[2*dtc][2]   * inv1, o[2*dtc][3]   * inv1);
        hh.z = packh(o[2*dtc+1][0] * inv0, o[2*dtc+1][1] * inv0);
        hh.w = packh(o[2*dtc+1][2] * inv1, o[2*dtc+1][3] * inv1);
        size_t idx = ((size_t)mtg * KT + h * 4 + dtc) * 32 + lane;
        g_yfh[idx] = hh;
    }
}

// ---------------------------------------------------------------------------
extern "C" void kernel_launch(void* const* d_in, const int* in_sizes, int n_in,
                              void* d_out, int out_size)
{
    const float* x  = (const float*)d_in[0];
    const float* Wq = (const float*)d_in[1];
    const float* bq = (const float*)d_in[2];
    const float* Wk = (const float*)d_in[3];
    const float* bk = (const float*)d_in[4];
    const float* Wv = (const float*)d_in[5];
    const float* bv = (const float*)d_in[6];
    const float* Wp = (const float*)d_in[7];
    const float* bp = (const float*)d_in[8];
    float* out = (float*)d_out;

    cudaFuncSetAttribute(qkv_mma, cudaFuncAttributeMaxDynamicSharedMemorySize, GEMM_SMEM_16);
    cudaFuncSetAttribute(proj_mma, cudaFuncAttributeMaxDynamicSharedMemorySize, GEMM_SMEM_16);
    cudaFuncSetAttribute(attn_mma, cudaFuncAttributeMaxDynamicSharedMemorySize, ATT_SMEM);

    split_xw_kernel<<<ACT_BLKS + W_BLKS, 256>>>(x, Wq, Wk, Wv, Wp);
    qkv_mma<<<dim3(Cn / 128, Mn / 128, 3), 256, GEMM_SMEM_16>>>(bq, bk, bv);
    attn_mma<<<dim3(Tn / 64, Hn, Bn), 128, ATT_SMEM>>>();
    proj_mma<<<dim3(Cn / 128, Mn / 128, 1), 256, GEMM_SMEM_16>>>(bp, out);
}

// round 17
// speedup vs baseline: 1.1042x; 1.0237x over previous
#include <cuda_runtime.h>
#include <cuda_fp16.h>
#include <cstdint>

static constexpr int Bn = 8, Tn = 1024, Cn = 768, Hn = 12, Dn = 64;
static constexpr int Mn = Bn * Tn;      // 8192
static constexpr int KT = Cn / 16;      // 48 k16 chunks
static constexpr int MT = Mn / 16;      // 512 m16 tiles
static constexpr int NTW = Cn / 8;      // 96 n8 tiles per weight matrix
static constexpr int BH = Bn * Hn;      // 96

// ---------------------------------------------------------------------------
// Scratch device globals
// ---------------------------------------------------------------------------
// A fragments (single fp16): [mt][tk][lane] -> uint4 (a0..a3)
__device__ uint4 g_xfh[MT * KT * 32];
__device__ uint4 g_yfh[MT * KT * 32];
// Weights B-frags (single fp16): [mat][nt][tk][lane] -> uint2 {b0,b1}
__device__ uint2 g_wf[4 * NTW * KT * 32];
// Q A-frags (single fp16, pre-scaled by log2e/8): [bh][mt(64)][dc(4)][lane]
__device__ uint4 g_qfh[BH * 64 * 4 * 32];
// K B-frags (single): [bh][nt(128)][dc(4)][lane]
__device__ uint2 g_kf[BH * 128 * 4 * 32];
// V^T B-frags (single): [bh][dt(8)][kc(64)][lane]
__device__ uint2 g_vtf[BH * 8 * 64 * 32];

// ---------------------------------------------------------------------------
// Helpers
// ---------------------------------------------------------------------------
__device__ __forceinline__ uint32_t smem_u32(const void* p) {
    uint32_t a;
    asm("{ .reg .u64 t; cvta.to.shared.u64 t, %1; cvt.u32.u64 %0, t; }"
        : "=r"(a) : "l"(p));
    return a;
}
__device__ __forceinline__ void cp16(uint32_t dst, const void* src) {
    asm volatile("cp.async.ca.shared.global [%0], [%1], 16;\n" :: "r"(dst), "l"(src));
}
__device__ __forceinline__ void cp8(uint32_t dst, const void* src) {
    asm volatile("cp.async.ca.shared.global [%0], [%1], 8;\n" :: "r"(dst), "l"(src));
}
#define CP_COMMIT() asm volatile("cp.async.commit_group;\n" ::: "memory")
#define CP_WAIT2()  asm volatile("cp.async.wait_group 2;\n" ::: "memory")
#define CP_WAIT1()  asm volatile("cp.async.wait_group 1;\n" ::: "memory")

__device__ __forceinline__ void mma16816(float* d, const uint32_t* a,
                                         uint32_t b0, uint32_t b1) {
    asm volatile(
        "mma.sync.aligned.m16n8k16.row.col.f32.f16.f16.f32 "
        "{%0,%1,%2,%3}, {%4,%5,%6,%7}, {%8,%9}, {%0,%1,%2,%3};\n"
        : "+f"(d[0]), "+f"(d[1]), "+f"(d[2]), "+f"(d[3])
        : "r"(a[0]), "r"(a[1]), "r"(a[2]), "r"(a[3]), "r"(b0), "r"(b1));
}

__device__ __forceinline__ uint32_t packh(float x, float y) {
    __half2 h = __floats2half2_rn(x, y);
    return *reinterpret_cast<uint32_t*>(&h);
}

// ---------------------------------------------------------------------------
// Combined input split: x -> single fp16 A-frags; W -> single fp16 B-frags
// ---------------------------------------------------------------------------
static constexpr int ACT_BLKS = (MT * KT) / 8;          // 3072
static constexpr int W_BLKS   = (4 * NTW * KT) / 8;     // 2304

__global__ __launch_bounds__(256)
void split_xw_kernel(const float* __restrict__ X,
                     const float* __restrict__ Wq, const float* __restrict__ Wk,
                     const float* __restrict__ Wv, const float* __restrict__ Wp)
{
    int lane = threadIdx.x & 31;
    if (blockIdx.x < ACT_BLKS) {
        int w = (blockIdx.x * 256 + threadIdx.x) >> 5;
        int tm = w / KT, tk = w % KT;
        int row = tm * 16 + (lane >> 2);
        int kc  = tk * 16 + ((lane & 3) << 1);

        float2 v00 = *(const float2*)(X + (size_t)row * Cn + kc);
        float2 v10 = *(const float2*)(X + (size_t)(row + 8) * Cn + kc);
        float2 v01 = *(const float2*)(X + (size_t)row * Cn + kc + 8);
        float2 v11 = *(const float2*)(X + (size_t)(row + 8) * Cn + kc + 8);

        uint4 h;
        h.x = packh(v00.x, v00.y);
        h.y = packh(v10.x, v10.y);
        h.z = packh(v01.x, v01.y);
        h.w = packh(v11.x, v11.y);
        g_xfh[(size_t)w * 32 + lane] = h;
    } else {
        int w = ((blockIdx.x - ACT_BLKS) * 256 + threadIdx.x) >> 5;
        int mat = w / (NTW * KT);
        int rem = w % (NTW * KT);
        int tn = rem / KT, tk = rem % KT;

        const float* W;
        switch (mat) {
            case 0: W = Wq; break;
            case 1: W = Wk; break;
            case 2: W = Wv; break;
            default: W = Wp; break;
        }
        int n  = tn * 8 + (lane >> 2);
        int k0 = tk * 16 + ((lane & 3) << 1);

        uint2 o;
        o.x = packh(W[(size_t)k0 * Cn + n], W[(size_t)(k0 + 1) * Cn + n]);
        o.y = packh(W[(size_t)(k0 + 8) * Cn + n], W[(size_t)(k0 + 9) * Cn + n]);
        g_wf[(size_t)w * 32 + lane] = o;
    }
}

// ---------------------------------------------------------------------------
// fp16 tensor-core GEMM (single-A), templated on NT = n8-tiles per CTA.
// NT=16: 128x128 tile (qkv). NT=24: 128x192 tile (proj) — 256 CTAs fit in
// ONE wave (296 slots), makespan = 1.5xT128 instead of 2 waves.
// 256 threads (8 warps: 4m x 2n). 4-stage cp.async pipeline.
// Stage layout: A [0,4K) mt*512+lane*16, B [4K,4K+NT*256) nt*256+lane*8.
// B copy (cp16): lanes 0..15 carry tile cp_t, lanes 16..31 carry cp_t+8;
// for NT>16 lanes 0..15 additionally carry tile cp_t+16.
// Epilogue modes: 0 = fp32 (+bias) to Out; 1 = Q A-frags (single fp16,
// scale log2e/8); 2 = K B-frags; 3 = V^T B-frags via smem fp16 transpose.
// ---------------------------------------------------------------------------
static constexpr int GEMM_SMEM_16 = 40960;  // 4 x 8KB stages + V^T headroom
static constexpr int GEMM_SMEM_24 = 40960;  // 4 x 10KB stages

template <int NT>
__device__ __forceinline__ void gemm_mma_body(const uint4* __restrict__ Ah,
                                              const uint2* __restrict__ Wf,
                                              const float* __restrict__ bias,
                                              float* __restrict__ Out,
                                              int mode)
{
    constexpr int STG = 4096 + NT * 256;   // stage bytes
    constexpr int NW  = NT / 2;            // n8-tiles per warp

    extern __shared__ __align__(16) char smem[];
    const uint32_t sbase = smem_u32(smem);
    const int tid  = threadIdx.x;
    const int lane = tid & 31;
    const int wid  = tid >> 5;
    const int wm   = wid >> 1;
    const int wn   = wid & 1;

    const int mtBase = blockIdx.y * 8;
    const int ntBase = blockIdx.x * NT;
    const int cp_t   = wid;

    // B copy roles (cp16 each)
    const int  bl   = lane & 15;
    const bool loB  = (lane < 16);
    const bool actB = loB || (cp_t < NT - 8);
    const bool actB2 = (NT > 16) && loB && (cp_t + 16 < NT);

    const uint4* srcAh = Ah + ((size_t)(mtBase + cp_t) * KT) * 32 + lane;
    const uint2* srcB  = Wf + ((size_t)(ntBase + cp_t + (loB ? 0 : 8)) * KT) * 32
                            + 2 * bl;
    const uint2* srcB2 = Wf + ((size_t)(ntBase + cp_t + 16) * KT) * 32 + 2 * bl;

    const uint32_t dA0 = sbase + cp_t * 512 + lane * 16;
    const uint32_t dB  = sbase + 4096 + cp_t * 256 + (loB ? 0u : 2048u) + bl * 16;
    const uint32_t dB2 = sbase + 4096 + (cp_t + 16) * 256 + bl * 16;

    float d[2][NW][4];
#pragma unroll
    for (int i = 0; i < 2; i++)
#pragma unroll
        for (int j = 0; j < NW; j++)
#pragma unroll
            for (int e = 0; e < 4; e++) d[i][j][e] = 0.f;

    auto issue = [&](int slot, int tk) {
        uint32_t so = (uint32_t)slot * STG;
        cp16(dA0 + so, srcAh + (size_t)tk * 32);
        if (actB)  cp16(dB + so,  srcB + (size_t)tk * 32);
        if (actB2) cp16(dB2 + so, srcB2 + (size_t)tk * 32);
    };

    issue(0, 0); CP_COMMIT();
    issue(1, 1); CP_COMMIT();
    issue(2, 2); CP_COMMIT();

    for (int k = 0; k < KT; k++) {
        CP_WAIT2();
        __syncthreads();
        if (k + 3 < KT) issue((k + 3) & 3, k + 3);
        CP_COMMIT();

        const char* stg = smem + (size_t)(k & 3) * STG;
        uint4 ah0 = *(const uint4*)(stg + (wm * 2 + 0) * 512 + lane * 16);
        uint4 ah1 = *(const uint4*)(stg + (wm * 2 + 1) * 512 + lane * 16);
#pragma unroll
        for (int nt = 0; nt < NW; nt++) {
            uint2 b = *(const uint2*)(stg + 4096 + (wn * NW + nt) * 256 + lane * 8);
            mma16816(d[0][nt], (const uint32_t*)&ah0, b.x, b.y);
            mma16816(d[1][nt], (const uint32_t*)&ah1, b.x, b.y);
        }
    }

    const int cb = blockIdx.x * (NT * 8) + wn * (NW * 8) + ((lane & 3) << 1);
    const int h  = blockIdx.x * 2 + wn;   // head (modes 1/2/3)

    if (NT == 16 && mode == 3) {
        // V^T fragments via smem fp16 transpose (row stride 136 halves).
        __syncthreads();
        __half* sv = reinterpret_cast<__half*>(smem);
#pragma unroll
        for (int mt = 0; mt < 2; mt++) {
            int r = wm * 32 + mt * 16 + (lane >> 2);
#pragma unroll
            for (int nt = 0; nt < NW; nt++) {
                int cl  = wn * 64 + nt * 8 + ((lane & 3) << 1);
                int col = blockIdx.x * 128 + cl;
                float bx = bias[col], by = bias[col + 1];
                *(__half2*)&sv[r * 136 + cl] =
                    __floats2half2_rn(d[mt][nt][0] + bx, d[mt][nt][1] + by);
                *(__half2*)&sv[(r + 8) * 136 + cl] =
                    __floats2half2_rn(d[mt][nt][2] + bx, d[mt][nt][3] + by);
            }
        }
        __syncthreads();
        const ushort* su = reinterpret_cast<const ushort*>(sv);
        const int bb  = blockIdx.y >> 3;
        const int kcb = (blockIdx.y & 7) * 8;
        const int dt  = wid;
#pragma unroll
        for (int hh = 0; hh < 2; hh++) {
            int dl  = hh * 64 + dt * 8 + (lane >> 2);
            int bh2 = bb * Hn + blockIdx.x * 2 + hh;
#pragma unroll
            for (int kl = 0; kl < 8; kl++) {
                int k0 = kl * 16 + ((lane & 3) << 1);
                uint2 o;
                o.x = (uint32_t)su[k0 * 136 + dl] |
                      ((uint32_t)su[(k0 + 1) * 136 + dl] << 16);
                o.y = (uint32_t)su[(k0 + 8) * 136 + dl] |
                      ((uint32_t)su[(k0 + 9) * 136 + dl] << 16);
                g_vtf[(((size_t)bh2 * 8 + dt) * 64 + kcb + kl) * 32 + lane] = o;
            }
        }
        return;
    }

#pragma unroll
    for (int mt = 0; mt < 2; mt++) {
        const int rg = blockIdx.y * 128 + wm * 32 + mt * 16;
        if (mode == 0) {
            const int r0 = rg + (lane >> 2);
#pragma unroll
            for (int nt = 0; nt < NW; nt++) {
                int col = cb + nt * 8;
                float bx = bias[col], by = bias[col + 1];
                *(float2*)(Out + (size_t)r0 * Cn + col) =
                    make_float2(d[mt][nt][0] + bx, d[mt][nt][1] + by);
                *(float2*)(Out + (size_t)(r0 + 8) * Cn + col) =
                    make_float2(d[mt][nt][2] + bx, d[mt][nt][3] + by);
            }
        } else if (NT == 16 && mode == 1) {
            // Q A-fragments (single fp16): scale log2e/8, bias folded
            const float QS = 0.18033688f;   // 0.125 * log2(e)
            const int bq_ = rg >> 10;
            const int mtq = (rg & 1023) >> 4;
            const size_t base =
                ((size_t)((bq_ * Hn + h) * 64 + mtq) * 4) * 32 + lane;
#pragma unroll
            for (int dc = 0; dc < 4; dc++) {
                int c0 = cb + (2 * dc) * 8, c1 = cb + (2 * dc + 1) * 8;
                float b00 = bias[c0], b01 = bias[c0 + 1];
                float b10 = bias[c1], b11 = bias[c1 + 1];
                uint4 hh;
                hh.x = packh((d[mt][2*dc][0]   + b00) * QS,
                             (d[mt][2*dc][1]   + b01) * QS);
                hh.y = packh((d[mt][2*dc][2]   + b00) * QS,
                             (d[mt][2*dc][3]   + b01) * QS);
                hh.z = packh((d[mt][2*dc+1][0] + b10) * QS,
                             (d[mt][2*dc+1][1] + b11) * QS);
                hh.w = packh((d[mt][2*dc+1][2] + b10) * QS,
                             (d[mt][2*dc+1][3] + b11) * QS);
                g_qfh[base + dc * 32] = hh;
            }
        } else if (NT == 16) {
            // K B-fragments (single fp16): two n8 key-tiles per m16
            const int bq_ = rg >> 10;
            const int ntk = (rg & 1023) >> 3;
            const size_t base =
                ((size_t)((bq_ * Hn + h) * 128 + ntk) * 4) * 32 + lane;
#pragma unroll
            for (int dc = 0; dc < 4; dc++) {
                int c0 = cb + (2 * dc) * 8, c1 = cb + (2 * dc + 1) * 8;
                float b00 = bias[c0], b01 = bias[c0 + 1];
                float b10 = bias[c1], b11 = bias[c1 + 1];
                uint2 t0, t1;
                t0.x = packh(d[mt][2*dc][0]   + b00, d[mt][2*dc][1]   + b01);
                t0.y = packh(d[mt][2*dc+1][0] + b10, d[mt][2*dc+1][1] + b11);
                t1.x = packh(d[mt][2*dc][2]   + b00, d[mt][2*dc][3]   + b01);
                t1.y = packh(d[mt][2*dc+1][2] + b10, d[mt][2*dc+1][3] + b11);
                g_kf[base + dc * 32]          = t0;
                g_kf[base + 4 * 32 + dc * 32] = t1;
            }
        }
    }
}

__global__ __launch_bounds__(256, 2)
void qkv_mma(const float* __restrict__ bq, const float* __restrict__ bk,
             const float* __restrict__ bv)
{
    const uint2* Wf = g_wf + (size_t)blockIdx.z * NTW * KT * 32;
    if (blockIdx.z == 0)      gemm_mma_body<16>(g_xfh, Wf, bq, nullptr, 1);
    else if (blockIdx.z == 1) gemm_mma_body<16>(g_xfh, Wf, bk, nullptr, 2);
    else                      gemm_mma_body<16>(g_xfh, Wf, bv, nullptr, 3);
}

__global__ __launch_bounds__(256, 2)
void proj_mma(const float* __restrict__ bp, float* __restrict__ out)
{
    gemm_mma_body<24>(g_yfh, g_wf + (size_t)3 * NTW * KT * 32, bp, out, 0);
}

// ---------------------------------------------------------------------------
// fp16 tensor-core flash attention. exp2-domain softmax (log2e folded into Q).
// Block = (64 q-rows, head, batch), 128 threads = 4 warps (m16 each).
// K tile: contiguous 8KB via cp16. V tile: 4 x cp16 per warp (256B chunks).
// CTA order reversed so the longest q-tiles launch first.
// ---------------------------------------------------------------------------
static constexpr int ATT_STG  = 16384;
static constexpr int ATT_SMEM = 3 * ATT_STG;   // 48KB

__global__ __launch_bounds__(128, 1)
void attn_mma()
{
    extern __shared__ __align__(16) char smem[];
    const uint32_t sbase = smem_u32(smem);
    const int tid  = threadIdx.x;
    const int lane = tid & 31;
    const int w    = tid >> 5;
    const int qt   = gridDim.x - 1 - blockIdx.x;
    const int h    = blockIdx.y;
    const int b    = blockIdx.z;
    const int bh   = b * Hn + h;
    const int nkt  = qt + 1;

    uint4 qh[4];
    {
        const uint4* Qh = g_qfh + ((size_t)(bh * 64 + qt * 4 + w) * 4) * 32 + lane;
#pragma unroll
        for (int dc = 0; dc < 4; dc++) qh[dc] = Qh[dc * 32];
    }

    float o[8][4];
#pragma unroll
    for (int i = 0; i < 8; i++)
#pragma unroll
        for (int j = 0; j < 4; j++) o[i][j] = 0.f;
    float m[2] = {-1e30f, -1e30f}, l[2] = {0.f, 0.f};

    const uint2* Ksrc = g_kf  + (size_t)bh * 128 * 4 * 32;
    const uint2* Vsrc = g_vtf + (size_t)bh * 8 * 64 * 32;
    const int vkc = w;

    auto issue = [&](int slot, int kt) {
        uint32_t so = sbase + (uint32_t)slot * ATT_STG;
        // K tile: contiguous 8KB in both gmem and smem -> 4 x cp16
        const char* ksb = (const char*)(Ksrc + (size_t)kt * 1024);
#pragma unroll
        for (int j = 0; j < 4; j++)
            cp16(so + (uint32_t)(j * 128 + tid) * 16, ksb + (size_t)(j * 128 + tid) * 16);
        // V tile: per-warp vkc slot, 8 dt chunks of 256B -> 4 x cp16
#pragma unroll
        for (int i2 = 0; i2 < 4; i2++) {
            int idx = i2 * 32 + lane;   // 0..127
            int dt  = idx >> 4;         // 0..7
            int o16 = idx & 15;         // 16B chunk within 256B
            cp16(so + 8192 + (uint32_t)((dt * 4 + vkc) * 256 + o16 * 16),
                 (const char*)(Vsrc + ((size_t)dt * 64 + kt * 4 + vkc) * 32) + o16 * 16);
        }
    };

    issue(0, 0); CP_COMMIT();
    if (nkt > 1) issue(1, 1);
    CP_COMMIT();

    for (int kt = 0; kt < nkt; kt++) {
        CP_WAIT1();
        __syncthreads();
        if (kt + 2 < nkt) issue((kt + 2) % 3, kt + 2);
        CP_COMMIT();

        const char* stK = smem + (size_t)(kt % 3) * ATT_STG;
        const char* stV = stK + 8192;

        // S = Q @ K^T (both single fp16; logits in log2 domain)
        float s[8][4];
#pragma unroll
        for (int i = 0; i < 8; i++)
#pragma unroll
            for (int j = 0; j < 4; j++) s[i][j] = 0.f;
#pragma unroll
        for (int dc = 0; dc < 4; dc++) {
#pragma unroll
            for (int nt = 0; nt < 8; nt++) {
                uint2 kb = *(const uint2*)(stK + ((nt * 4 + dc) * 32 + lane) * 8);
                mma16816(s[nt], (const uint32_t*)&qh[dc], kb.x, kb.y);
            }
        }

        // Causal mask (diagonal tile only)
        if (kt == qt) {
            int r0 = w * 16 + (lane >> 2);
            int c0 = (lane & 3) << 1;
#pragma unroll
            for (int nt = 0; nt < 8; nt++) {
                int col = nt * 8 + c0;
                if (col > r0)         s[nt][0] = -1e30f;
                if (col + 1 > r0)     s[nt][1] = -1e30f;
                if (col > r0 + 8)     s[nt][2] = -1e30f;
                if (col + 1 > r0 + 8) s[nt][3] = -1e30f;
            }
        }

        // Online softmax per row-half (exp2 domain)
#pragma unroll
        for (int i = 0; i < 2; i++) {
            float tm = -1e30f;
#pragma unroll
            for (int nt = 0; nt < 8; nt++)
                tm = fmaxf(tm, fmaxf(s[nt][2 * i], s[nt][2 * i + 1]));
            tm = fmaxf(tm, __shfl_xor_sync(0xffffffffu, tm, 1));
            tm = fmaxf(tm, __shfl_xor_sync(0xffffffffu, tm, 2));
            float newm = fmaxf(m[i], tm);
            float fac  = exp2f(m[i] - newm);
            m[i] = newm;
            float rs = 0.f;
#pragma unroll
            for (int nt = 0; nt < 8; nt++) {
                float p0 = exp2f(s[nt][2 * i] - newm);
                float p1 = exp2f(s[nt][2 * i + 1] - newm);
                s[nt][2 * i] = p0;
                s[nt][2 * i + 1] = p1;
                rs += p0 + p1;
            }
            rs += __shfl_xor_sync(0xffffffffu, rs, 1);
            rs += __shfl_xor_sync(0xffffffffu, rs, 2);
            l[i] = l[i] * fac + rs;
#pragma unroll
            for (int dt = 0; dt < 8; dt++) {
                o[dt][2 * i]     *= fac;
                o[dt][2 * i + 1] *= fac;
            }
        }

        // O += P @ V  (P single fp16)
#pragma unroll
        for (int t = 0; t < 4; t++) {
            uint32_t ph[4];
            ph[0] = packh(s[2*t][0],   s[2*t][1]);
            ph[1] = packh(s[2*t][2],   s[2*t][3]);
            ph[2] = packh(s[2*t+1][0], s[2*t+1][1]);
            ph[3] = packh(s[2*t+1][2], s[2*t+1][3]);
#pragma unroll
            for (int dt = 0; dt < 8; dt++) {
                uint2 v = *(const uint2*)(stV + ((dt * 4 + t) * 32 + lane) * 8);
                mma16816(o[dt], ph, v.x, v.y);
            }
        }
    }

    // Epilogue: normalize, write y A-fragments (single fp16) for proj GEMM
    const float inv0 = 1.f / l[0];
    const float inv1 = 1.f / l[1];
    const int mtg = b * 64 + qt * 4 + w;
#pragma unroll
    for (int dtc = 0; dtc < 4; dtc++) {
        uint4 hh;
        hh.x = packh(o[2*dtc][0]   * inv0, o[2*dtc][1]   * inv0);
        hh.y = packh(o[2*dtc][2]   * inv1, o[2*dtc][3]   * inv1);
        hh.z = packh(o[2*dtc+1][0] * inv0, o[2*dtc+1][1] * inv0);
        hh.w = packh(o[2*dtc+1][2] * inv1, o[2*dtc+1][3] * inv1);
        size_t idx = ((size_t)mtg * KT + h * 4 + dtc) * 32 + lane;
        g_yfh[idx] = hh;
    }
}

// ---------------------------------------------------------------------------
extern "C" void kernel_launch(void* const* d_in, const int* in_sizes, int n_in,
                              void* d_out, int out_size)
{
    const float* x  = (const float*)d_in[0];
    const float* Wq = (const float*)d_in[1];
    const float* bq = (const float*)d_in[2];
    const float* Wk = (const float*)d_in[3];
    const float* bk = (const float*)d_in[4];
    const float* Wv = (const float*)d_in[5];
    const float* bv = (const float*)d_in[6];
    const float* Wp = (const float*)d_in[7];
    const float* bp = (const float*)d_in[8];
    float* out = (float*)d_out;

    cudaFuncSetAttribute(qkv_mma, cudaFuncAttributeMaxDynamicSharedMemorySize, GEMM_SMEM_16);
    cudaFuncSetAttribute(proj_mma, cudaFuncAttributeMaxDynamicSharedMemorySize, GEMM_SMEM_24);
    cudaFuncSetAttribute(attn_mma, cudaFuncAttributeMaxDynamicSharedMemorySize, ATT_SMEM);

    split_xw_kernel<<<ACT_BLKS + W_BLKS, 256>>>(x, Wq, Wk, Wv, Wp);
    qkv_mma<<<dim3(Cn / 128, Mn / 128, 3), 256, GEMM_SMEM_16>>>(bq, bk, bv);
    attn_mma<<<dim3(Tn / 64, Hn, Bn), 128, ATT_SMEM>>>();
    proj_mma<<<dim3(Cn / 192, Mn / 128, 1), 256, GEMM_SMEM_24>>>(bp, out);
}